// round 2
// baseline (speedup 1.0000x reference)
#include <cuda_runtime.h>

// Problem constants
#define FP          80
#define MTAPS       24
#define NSTAGES     20
#define BATCH       8
#define NFRAMES     1024
#define TLEN        (NFRAMES * FP)   // 81920

// Tiling: 256 threads x 8 samples = 2048-wide window, 2 blocks/SM
#define RPT         8                 // 8 | 80 -> one frame pair per thread
#define BLOCK       256
#define WINW        (BLOCK * RPT)     // 2048
#define HALO        (NSTAGES * MTAPS) // 480
#define TBOUT       (WINW - HALO)     // 1568
#define PADZ        24
#define BPB         ((TLEN + TBOUT - 1) / TBOUT)   // 53

__global__ void __launch_bounds__(BLOCK, 2)
fir_taylor_kernel(const float* __restrict__ x,
                  const float* __restrict__ mc,
                  const float* __restrict__ a,
                  const float* __restrict__ wts,
                  float* __restrict__ out)
{
    __shared__ float buf0[WINW + PADZ];
    __shared__ float buf1[WINW + PADZ];
    __shared__ float s_a[NSTAGES + 1];
    __shared__ float s_w[NSTAGES + 1];

    const int tid = threadIdx.x;
    const int blk = blockIdx.x;
    const int b   = blk / BPB;
    const int tb  = blk % BPB;
    const int t0  = tb * TBOUT;
    const int g0  = t0 - HALO;

    if (tid <= NSTAGES) { s_a[tid] = a[tid]; s_w[tid] = wts[tid]; }
    if (tid < PADZ)     { buf0[tid] = 0.0f; buf1[tid] = 0.0f; }

    const float* xb = x + b * TLEN;
    for (int p = tid; p < WINW; p += BLOCK) {
        int t = g0 + p;
        buf0[PADZ + p] = (t >= 0 && t < TLEN) ? xb[t] : 0.0f;
    }

    // ---- per-thread coefficients (registers, stage-invariant) ----
    const int lp    = tid * RPT;
    const int tbase = g0 + lp;
    int tc = tbase < 0 ? 0 : (tbase >= TLEN ? TLEN - 1 : tbase);
    int n  = tc / FP;
    int n1 = (n + 1 < NFRAMES) ? n + 1 : NFRAMES - 1;
    const float invP = 1.0f / (float)FP;
    const float w0   = (float)(tc - n * FP) * invP;

    const float* mrow0 = mc + ((long)b * NFRAMES + n)  * (MTAPS + 1);
    const float* mrow1 = mc + ((long)b * NFRAMES + n1) * (MTAPS + 1);

    float cc[MTAPS], dp[MTAPS];
#pragma unroll
    for (int j = 0; j < MTAPS; j++) {
        float c0v = mrow0[j + 1];
        float c1v = mrow1[j + 1];
        float d   = c1v - c0v;
        cc[j] = fmaf(w0, d, c0v);    // coefficient at r = 0
        dp[j] = d * invP;            // per-sample increment
    }
    const float k0 = mrow0[0];
    const float dk = mrow1[0] - k0;

    __syncthreads();

    // own samples -> registers; y = x*a[0]
    float acc[RPT];
    float y[RPT];
    {
        const float a0 = s_a[0];
        const float4* v = (const float4*)(buf0 + PADZ + lp);
#pragma unroll
        for (int q = 0; q < RPT / 4; q++) {
            float4 f = v[q];
            acc[4*q+0] = f.x; acc[4*q+1] = f.y; acc[4*q+2] = f.z; acc[4*q+3] = f.w;
        }
#pragma unroll
        for (int r = 0; r < RPT; r++) y[r] = acc[r] * a0;
    }

    float* cur = buf0;
    float* nxt = buf1;

    for (int i = 1; i <= NSTAGES; i++) {
        const float wgt = s_w[i];
        const float ai  = s_a[i];

        // window: 24 halo floats from smem + 8 own values from regs
        float win[RPT + MTAPS];
        const float4* v = (const float4*)(cur + PADZ + lp - MTAPS);
#pragma unroll
        for (int q = 0; q < MTAPS / 4; q++) {
            float4 f = v[q];
            win[4*q+0] = f.x; win[4*q+1] = f.y; win[4*q+2] = f.z; win[4*q+3] = f.w;
        }
#pragma unroll
        for (int r = 0; r < RPT; r++) win[MTAPS + r] = acc[r];

        float nacc[RPT];
#pragma unroll
        for (int r = 0; r < RPT; r++) {
            const float fr = (float)r;
            float s = 0.0f;
#pragma unroll
            for (int j = 1; j <= MTAPS; j++) {
                float coef = fmaf(fr, dp[j - 1], cc[j - 1]);
                s = fmaf(win[MTAPS + r - j], coef, s);
            }
            nacc[r] = s * wgt;
            y[r]    = fmaf(nacc[r], ai, y[r]);
        }

#pragma unroll
        for (int r = 0; r < RPT; r++) acc[r] = nacc[r];

        if (i < NSTAGES) {  // last stage needs no publish
            float4* st = (float4*)(nxt + PADZ + lp);
#pragma unroll
            for (int q = 0; q < RPT / 4; q++) {
                float4 f;
                f.x = acc[4*q+0]; f.y = acc[4*q+1]; f.z = acc[4*q+2]; f.w = acc[4*q+3];
                st[q] = f;
            }
            __syncthreads();
            float* tmp = cur; cur = nxt; nxt = tmp;
        }
    }

    // ---- epilogue: out = y * exp(interp(mc[...,0])) ----
    if (lp >= HALO) {
        float* ob = out + b * TLEN;
#pragma unroll
        for (int r = 0; r < RPT; r++) {
            int tt = tbase + r;
            if (tt < TLEN) {
                float K = expf(fmaf(w0 + (float)r * invP, dk, k0));
                ob[tt] = y[r] * K;
            }
        }
    }
}

extern "C" void kernel_launch(void* const* d_in, const int* in_sizes, int n_in,
                              void* d_out, int out_size)
{
    (void)in_sizes; (void)n_in; (void)out_size;
    const float* x   = (const float*)d_in[0];
    const float* mc  = (const float*)d_in[1];
    const float* a   = (const float*)d_in[2];
    const float* wts = (const float*)d_in[3];
    float* out = (float*)d_out;

    fir_taylor_kernel<<<BATCH * BPB, BLOCK>>>(x, mc, a, wts, out);
}

// round 3
// speedup vs baseline: 1.9348x; 1.9348x over previous
#include <cuda_runtime.h>

#define FP      80
#define MTAPS   24
#define NSTAGES 20
#define BATCH   8
#define NFRAMES 1024
#define TLEN    (NFRAMES * FP)        // 81920

#define RPT     4                     // 4 | 80 -> thread never crosses a frame
#define BLOCK   448
#define WINW    (BLOCK * RPT)         // 1792
#define HALO    (NSTAGES * MTAPS)     // 480
#define TBOUT   (WINW - HALO)         // 1312
#define PADZ    24
#define BPB     ((TLEN + TBOUT - 1) / TBOUT)   // 63

typedef unsigned long long u64p;

__device__ __forceinline__ u64p pk2(float lo, float hi) {
    u64p r; asm("mov.b64 %0, {%1, %2};" : "=l"(r) : "f"(lo), "f"(hi)); return r;
}
__device__ __forceinline__ void upk2(u64p v, float& lo, float& hi) {
    asm("mov.b64 {%0, %1}, %2;" : "=f"(lo), "=f"(hi) : "l"(v));
}
__device__ __forceinline__ u64p ffma2(u64p a, u64p b, u64p c) {
    u64p d; asm("fma.rn.f32x2 %0, %1, %2, %3;" : "=l"(d) : "l"(a), "l"(b), "l"(c)); return d;
}
__device__ __forceinline__ u64p fmul2(u64p a, u64p b) {
    u64p d; asm("mul.rn.f32x2 %0, %1, %2;" : "=l"(d) : "l"(a), "l"(b)); return d;
}
__device__ __forceinline__ u64p fadd2(u64p a, u64p b) {
    u64p d; asm("add.rn.f32x2 %0, %1, %2;" : "=l"(d) : "l"(a), "l"(b)); return d;
}

__global__ void __launch_bounds__(BLOCK, 1)
fir_taylor_kernel(const float* __restrict__ x,
                  const float* __restrict__ mc,
                  const float* __restrict__ a,
                  const float* __restrict__ wts,
                  float* __restrict__ out)
{
    __shared__ float buf0[WINW + PADZ];
    __shared__ float buf1[WINW + PADZ];
    __shared__ float s_a[NSTAGES + 1];
    __shared__ float s_w[NSTAGES + 1];

    const int tid = threadIdx.x;
    const int blk = blockIdx.x;
    const int b   = blk / BPB;
    const int tb  = blk % BPB;
    const int t0  = tb * TBOUT;
    const int g0  = t0 - HALO;

    if (tid <= NSTAGES) { s_a[tid] = a[tid]; s_w[tid] = wts[tid]; }
    if (tid < PADZ)     { buf0[tid] = 0.0f; buf1[tid] = 0.0f; }

    const float* xb = x + b * TLEN;
    for (int p = tid; p < WINW; p += BLOCK) {
        int t = g0 + p;
        buf0[PADZ + p] = (t >= 0 && t < TLEN) ? xb[t] : 0.0f;
    }

    // ---- stage-invariant packed coefficients (registers) ----
    const int lp    = tid * RPT;
    const int tbase = g0 + lp;
    int tc = tbase < 0 ? 0 : (tbase >= TLEN ? TLEN - 1 : tbase);
    int n  = tc / FP;
    int n1 = (n + 1 < NFRAMES) ? n + 1 : NFRAMES - 1;
    const float invP = 1.0f / (float)FP;
    const float w0   = (float)(tc - n * FP) * invP;
    const float w1   = w0 + invP;
    const float w2   = w0 + 2.0f * invP;
    const float w3   = w0 + 3.0f * invP;

    const float* mrow0 = mc + ((long)b * NFRAMES + n)  * (MTAPS + 1);
    const float* mrow1 = mc + ((long)b * NFRAMES + n1) * (MTAPS + 1);

    u64p cc01[MTAPS], cc23[MTAPS];
#pragma unroll
    for (int j = 0; j < MTAPS; j++) {
        float c0v = mrow0[j + 1];
        float d   = mrow1[j + 1] - c0v;
        cc01[j] = pk2(fmaf(w0, d, c0v), fmaf(w1, d, c0v));
        cc23[j] = pk2(fmaf(w2, d, c0v), fmaf(w3, d, c0v));
    }
    const float k0 = mrow0[0];
    const float dk = mrow1[0] - k0;

    __syncthreads();

    // own samples + y init
    float acc0, acc1, acc2, acc3;
    {
        float4 f = *((const float4*)(buf0 + PADZ + lp));
        acc0 = f.x; acc1 = f.y; acc2 = f.z; acc3 = f.w;
    }
    u64p a0p = pk2(s_a[0], s_a[0]);
    u64p y01 = fmul2(pk2(acc0, acc1), a0p);
    u64p y23 = fmul2(pk2(acc2, acc3), a0p);

    float* cur = buf0;
    float* nxt = buf1;

    for (int i = 1; i <= NSTAGES; i++) {
        const float wgt = s_w[i];
        const float ai  = s_a[i];
        const u64p wgt2 = pk2(wgt, wgt);
        const u64p ai2  = pk2(ai, ai);

        // window: w[0..23] halo from smem (16B aligned), w[24..27] own regs
        float w[MTAPS + RPT];
        {
            const float4* v = (const float4*)(cur + PADZ + lp - MTAPS);
#pragma unroll
            for (int q = 0; q < MTAPS / 4; q++) {
                float4 f = v[q];
                w[4*q+0] = f.x; w[4*q+1] = f.y; w[4*q+2] = f.z; w[4*q+3] = f.w;
            }
        }
        w[24] = acc0; w[25] = acc1; w[26] = acc2; w[27] = acc3;

        // MAC: s(r) = sum_{j=1..24} w[24+r-j] * coef_j(r), packed over r-pairs.
        // Pair k = {w[k], w[k+1]}; r01 uses k=24-j at tap j, r23 reuses it 2 taps later.
        u64p s01a = 0, s01b = 0, s23a = 0, s23b = 0;
        u64p pm2 = pk2(w[25], w[26]);   // k=25 (r23, j=1)
        u64p pm1 = pk2(w[24], w[25]);   // k=24 (r23, j=2)
#pragma unroll
        for (int j = 1; j <= MTAPS; j++) {
            u64p pc = pk2(w[24 - j], w[25 - j]);   // k = 24-j
            if (j & 1) {
                s01a = ffma2(pc,  cc01[j - 1], s01a);
                s23a = ffma2(pm2, cc23[j - 1], s23a);
            } else {
                s01b = ffma2(pc,  cc01[j - 1], s01b);
                s23b = ffma2(pm2, cc23[j - 1], s23b);
            }
            pm2 = pm1; pm1 = pc;
        }
        u64p sc01 = fmul2(fadd2(s01a, s01b), wgt2);
        u64p sc23 = fmul2(fadd2(s23a, s23b), wgt2);
        y01 = ffma2(sc01, ai2, y01);
        y23 = ffma2(sc23, ai2, y23);

        upk2(sc01, acc0, acc1);
        upk2(sc23, acc2, acc3);

        if (i < NSTAGES) {
            float4 st; st.x = acc0; st.y = acc1; st.z = acc2; st.w = acc3;
            *((float4*)(nxt + PADZ + lp)) = st;
            __syncthreads();
            float* tmp = cur; cur = nxt; nxt = tmp;
        }
    }

    // ---- epilogue: out = y * exp(interp(mc[...,0])) for exact region ----
    if (lp >= HALO) {
        float yv[RPT];
        upk2(y01, yv[0], yv[1]);
        upk2(y23, yv[2], yv[3]);
        const float wr[RPT] = { w0, w1, w2, w3 };
        float* ob = out + b * TLEN;
#pragma unroll
        for (int r = 0; r < RPT; r++) {
            int tt = tbase + r;
            if (tt < TLEN) {
                float K = expf(fmaf(wr[r], dk, k0));
                ob[tt] = yv[r] * K;
            }
        }
    }
}

extern "C" void kernel_launch(void* const* d_in, const int* in_sizes, int n_in,
                              void* d_out, int out_size)
{
    (void)in_sizes; (void)n_in; (void)out_size;
    const float* x   = (const float*)d_in[0];
    const float* mc  = (const float*)d_in[1];
    const float* a   = (const float*)d_in[2];
    const float* wts = (const float*)d_in[3];
    float* out = (float*)d_out;

    fir_taylor_kernel<<<BATCH * BPB, BLOCK>>>(x, mc, a, wts, out);
}